// round 3
// baseline (speedup 1.0000x reference)
#include <cuda_runtime.h>

#define BB 32
#define LL 8192
#define DD 256
#define MM (LL/2 + 1)             // 4097
#define CH 32                     // rows per chunk
#define CHUNKS (LL / CH)          // 256
#define NBLK (BB * CHUNKS)        // 8192
#define OUT_ELEMS ((long long)BB * MM * DD)

// Scratch (no device allocation allowed)
__device__ volatile unsigned long long g_state[NBLK];  // look-back: flag<<32 | value
__device__ int g_counts[BB];

// ---------------------------------------------------------------------------
__global__ void init_kernel() {
    int i = blockIdx.x * blockDim.x + threadIdx.x;
    if (i < NBLK) g_state[i] = 0ull;
}

// ---------------------------------------------------------------------------
// Fused: per 32-row chunk — load x tile once, compute s (incl. halos),
// detect strict local minima, decoupled look-back for output offset,
// write pooled output rows directly from SMEM-resident x.
// ---------------------------------------------------------------------------
__global__ void __launch_bounds__(256) fused_kernel(
    const float* __restrict__ x, const float* __restrict__ W,
    const float* __restrict__ bias, float* __restrict__ out, int write_counts)
{
    __shared__ __align__(16) float sx[(CH + 1) * DD];   // chunk rows + halo (33 KB)
    __shared__ __align__(16) float sW[DD];
    __shared__ __align__(16) float ss[CH + 2];          // s for rows r0-1 .. r0+CH
    __shared__ int   s_list[CH];
    __shared__ int   s_ex, s_tot;

    int tid = threadIdx.x;
    int bid = blockIdx.x;
    int b = bid >> 8;                 // bid / CHUNKS
    int c = bid & (CHUNKS - 1);
    int r0 = c * CH;

    sW[tid] = W[tid];                 // blockDim == DD

    // --- load x tile (32 rows + halo row if it exists), coalesced float4 ---
    int nrows = (r0 + CH < LL) ? (CH + 1) : CH;
    const float4* xg4 = (const float4*)(x + ((long long)b * LL + r0) * DD);
    float4* sx4 = (float4*)sx;
    int n4 = nrows * (DD / 4);
    for (int i = tid; i < n4; i += 256) sx4[i] = xg4[i];
    __syncthreads();

    // --- compute s for rows r0-1 .. r0+CH : one warp-reduced dot per task ---
    int warp = tid >> 5, lane = tid & 31;
    float bv = bias[0];
    for (int j = warp; j < CH + 2; j += 8) {
        const float4* src = 0;
        bool valid = true;
        if (j == 0) {
            if (c == 0) valid = false;
            else src = (const float4*)(x + ((long long)b * LL + r0 - 1) * DD);
        } else {
            if (r0 + j - 1 >= LL) valid = false;
            else src = (const float4*)(sx + (j - 1) * DD);
        }
        float acc = 0.f;
        if (valid) {
            const float4* wv = (const float4*)sW;
#pragma unroll
            for (int k2 = 0; k2 < 2; k2++) {
                float4 v = src[lane * 2 + k2];
                float4 w = wv[lane * 2 + k2];
                acc += v.x * w.x + v.y * w.y + v.z * w.z + v.w * w.w;
            }
        }
#pragma unroll
        for (int o = 16; o; o >>= 1) acc += __shfl_down_sync(0xffffffffu, acc, o);
        if (lane == 0) ss[j] = valid ? (1.f / (1.f + expf(-(acc + bv)))) : 0.f;
    }
    __syncthreads();

    // --- mask + ballot-scan (warp 0), publish + look-back (thread 0) ---
    if (tid < 32) {
        int l = r0 + tid;
        bool m;
        if (l == 0)            m = true;     // forced valley start
        else if (l >= LL - 1)  m = false;    // s_after pad 0, sigmoid > 0
        else m = (ss[tid + 1] < ss[tid]) && (ss[tid + 1] < ss[tid + 2]);
        unsigned bits = __ballot_sync(0xffffffffu, m);
        int pfx = __popc(bits & ((1u << tid) - 1));
        int tot = __popc(bits);
        if (m) s_list[pfx] = tid;
        if (tid == 0) {
            long long ex = 0;
            if (c == 0) {
                g_state[bid] = (2ull << 32) | (unsigned)tot;   // prefix ready
            } else {
                g_state[bid] = (1ull << 32) | (unsigned)tot;   // aggregate ready
                int i = bid - 1;
                for (;;) {
                    unsigned long long v;
                    do { v = g_state[i]; } while (!(v >> 32));
                    ex += (unsigned)(v & 0xffffffffu);
                    if ((v >> 32) == 2ull) break;
                    --i;
                }
                g_state[bid] = (2ull << 32) | (unsigned)(ex + tot);
            }
            s_ex = (int)ex;
            s_tot = tot;
            if (c == CHUNKS - 1) {
                int tb = (int)ex + tot;
                g_counts[b] = tb;
                if (write_counts) out[OUT_ELEMS + b] = (float)tb;
            }
        }
    }
    __syncthreads();

    // --- write pooled rows: 4 rows in parallel, 64 threads per row ---
    int ex = s_ex;
    int tot = s_tot;
    int grp = tid >> 6;        // 0..3
    int col = tid & 63;        // float4 column
    for (int j0 = 0; j0 < tot; j0 += 4) {
        int j = j0 + grp;
        if (j < tot) {
            int lr = s_list[j];
            float s0 = ss[lr + 1], s1 = ss[lr + 2];
            float rden = 1.f / fmaxf(s0 + s1, 1e-6f);
            const float4* a0 = (const float4*)(sx + lr * DD);
            const float4* a1 = (const float4*)(sx + (lr + 1) * DD);
            float4 v0 = a0[col], v1 = a1[col];
            float4 o;
            o.x = (s0 * v0.x + s1 * v1.x) * rden;
            o.y = (s0 * v0.y + s1 * v1.y) * rden;
            o.z = (s0 * v0.z + s1 * v1.z) * rden;
            o.w = (s0 * v0.w + s1 * v1.w) * rden;
            ((float4*)out)[((long long)b * MM + ex + j) * (DD / 4) + col] = o;
        }
    }
}

// ---------------------------------------------------------------------------
// Zero the sentinel tail rows [count_b, MM) of each batch.
// ---------------------------------------------------------------------------
__global__ void zero_tail_kernel(float* __restrict__ out) {
    long long idx = (long long)blockIdx.x * blockDim.x + threadIdx.x;
    const long long total4 = (long long)BB * MM * (DD / 4);
    if (idx >= total4) return;
    long long row = idx >> 6;
    int b = (int)(row / MM);
    int k = (int)(row - (long long)b * MM);
    if (k >= g_counts[b]) {
        float4 z; z.x = 0.f; z.y = 0.f; z.z = 0.f; z.w = 0.f;
        ((float4*)out)[idx] = z;
    }
}

// ---------------------------------------------------------------------------
extern "C" void kernel_launch(void* const* d_in, const int* in_sizes, int n_in,
                              void* d_out, int out_size) {
    const float* x    = (const float*)d_in[0];   // [B, L, D] f32
    // d_in[1]: olens (unused)
    const float* W    = (const float*)d_in[2];   // [D, 1]
    const float* bias = (const float*)d_in[3];   // [1]

    float* out = (float*)d_out;
    int write_counts = (out_size >= (int)(OUT_ELEMS + BB)) ? 1 : 0;

    init_kernel<<<(NBLK + 255) / 256, 256>>>();
    fused_kernel<<<NBLK, 256>>>(x, W, bias, out, write_counts);
    {
        long long total4 = (long long)BB * MM * (DD / 4);
        int grid = (int)((total4 + 255) / 256);
        zero_tail_kernel<<<grid, 256>>>(out);
    }
}

// round 4
// speedup vs baseline: 1.2021x; 1.2021x over previous
#include <cuda_runtime.h>

#define BB 32
#define LL 8192
#define DD 256
#define MM (LL/2 + 1)             // 4097
#define CH 256                    // rows per chunk
#define CHUNKS (LL / CH)          // 32
#define NBLK (BB * CHUNKS)        // 1024
#define OUT_ELEMS ((long long)BB * MM * DD)
#define MAXV (CH/2 + 8)           // max valleys per chunk (strict minima non-adjacent)

// Scratch (no device allocation allowed)
__device__ volatile unsigned long long g_state[NBLK];  // look-back: flag<<32 | value
__device__ int g_counts[BB];

// ---------------------------------------------------------------------------
__global__ void init_kernel() {
    int i = blockIdx.x * blockDim.x + threadIdx.x;
    if (i < NBLK) g_state[i] = 0ull;
}

// ---------------------------------------------------------------------------
// Fused: per 256-row chunk — stream x for scores, detect strict local minima,
// decoupled look-back (32 links/batch) for output offset, then write pooled
// rows re-reading valley rows from global (L1/L2-resident: just touched).
// ---------------------------------------------------------------------------
__global__ void __launch_bounds__(256) fused_kernel(
    const float* __restrict__ x, const float* __restrict__ W,
    const float* __restrict__ bias, float* __restrict__ out, int write_counts)
{
    __shared__ __align__(16) float sW[DD];
    __shared__ float ss[CH + 2];          // s for rows r0-1 .. r0+CH
    __shared__ int   s_list[MAXV];
    __shared__ int   warpsum[8];
    __shared__ int   s_ex, s_tot;

    int tid = threadIdx.x;
    int bid = blockIdx.x;
    int b = bid / CHUNKS;
    int c = bid - b * CHUNKS;
    int r0 = c * CH;

    sW[tid] = W[tid];                     // blockDim == DD
    __syncthreads();

    // --- compute s for rows r0-1 .. r0+CH (258 warp-dot tasks, 8 warps) ---
    int warp = tid >> 5, lane = tid & 31;
    float bv = bias[0];
    const float* xb = x + (long long)b * LL * DD;
    const float4* wv = (const float4*)sW;
    for (int j = warp; j < CH + 2; j += 8) {
        int row = r0 + j - 1;
        bool valid = (row >= 0) && (row < LL);
        float acc = 0.f;
        if (valid) {
            const float4* src = (const float4*)(xb + (long long)row * DD);
            float4 v0 = src[lane * 2], w0 = wv[lane * 2];
            float4 v1 = src[lane * 2 + 1], w1 = wv[lane * 2 + 1];
            acc = v0.x * w0.x + v0.y * w0.y + v0.z * w0.z + v0.w * w0.w
                + v1.x * w1.x + v1.y * w1.y + v1.z * w1.z + v1.w * w1.w;
        }
#pragma unroll
        for (int o = 16; o; o >>= 1) acc += __shfl_down_sync(0xffffffffu, acc, o);
        if (lane == 0) ss[j] = valid ? (1.f / (1.f + expf(-(acc + bv)))) : 0.f;
    }
    __syncthreads();

    // --- mask + block scan: thread tid owns position l = r0 + tid ---
    {
        int l = r0 + tid;
        bool m;
        if (l == 0)            m = true;     // forced valley start
        else if (l >= LL - 1)  m = false;    // zero-pad neighbor, sigmoid > 0
        else m = (ss[tid + 1] < ss[tid]) && (ss[tid + 1] < ss[tid + 2]);

        unsigned bits = __ballot_sync(0xffffffffu, m);
        int pfx = __popc(bits & ((1u << lane) - 1));
        int wtot = __popc(bits);
        if (lane == 0) warpsum[warp] = wtot;
        __syncthreads();
        if (tid == 0) {
            int run = 0;
#pragma unroll
            for (int w = 0; w < 8; w++) { int t = warpsum[w]; warpsum[w] = run; run += t; }
            s_tot = run;
        }
        __syncthreads();
        if (m) s_list[warpsum[warp] + pfx] = tid;
    }

    // --- publish + decoupled look-back (thread 0) ---
    if (tid == 0) {
        int tot = s_tot;
        long long ex = 0;
        if (c == 0) {
            g_state[bid] = (2ull << 32) | (unsigned)tot;   // inclusive prefix ready
        } else {
            g_state[bid] = (1ull << 32) | (unsigned)tot;   // aggregate ready
            int i = bid - 1;
            for (;;) {
                unsigned long long v;
                do { v = g_state[i]; } while (!(v >> 32));
                ex += (unsigned)(v & 0xffffffffu);
                if ((v >> 32) == 2ull) break;
                --i;
            }
            g_state[bid] = (2ull << 32) | (unsigned)(ex + tot);
        }
        s_ex = (int)ex;
        if (c == CHUNKS - 1) {
            int tb = (int)ex + tot;
            g_counts[b] = tb;
            if (write_counts) out[OUT_ELEMS + b] = (float)tb;
        }
    }
    __syncthreads();

    // --- write pooled rows: 4 rows in parallel, 64 threads per row ---
    int ex = s_ex;
    int tot = s_tot;
    int grp = tid >> 6;        // 0..3
    int col = tid & 63;        // float4 column
    for (int j0 = 0; j0 < tot; j0 += 4) {
        int j = j0 + grp;
        if (j < tot) {
            int lr = s_list[j];
            int p = r0 + lr;                      // valley start, p+1 < LL guaranteed
            float s0 = ss[lr + 1], s1 = ss[lr + 2];
            float rden = 1.f / fmaxf(s0 + s1, 1e-6f);
            const float4* a = (const float4*)(xb + (long long)p * DD);
            float4 v0 = a[col];
            float4 v1 = a[(DD / 4) + col];
            float4 o;
            o.x = (s0 * v0.x + s1 * v1.x) * rden;
            o.y = (s0 * v0.y + s1 * v1.y) * rden;
            o.z = (s0 * v0.z + s1 * v1.z) * rden;
            o.w = (s0 * v0.w + s1 * v1.w) * rden;
            ((float4*)out)[((long long)b * MM + ex + j) * (DD / 4) + col] = o;
        }
    }
}

// ---------------------------------------------------------------------------
// Zero the sentinel tail rows [count_b, MM) of each batch.
// ---------------------------------------------------------------------------
__global__ void zero_tail_kernel(float* __restrict__ out) {
    long long idx = (long long)blockIdx.x * blockDim.x + threadIdx.x;
    const long long total4 = (long long)BB * MM * (DD / 4);
    if (idx >= total4) return;
    long long row = idx >> 6;
    int b = (int)(row / MM);
    int k = (int)(row - (long long)b * MM);
    if (k >= g_counts[b]) {
        float4 z; z.x = 0.f; z.y = 0.f; z.z = 0.f; z.w = 0.f;
        ((float4*)out)[idx] = z;
    }
}

// ---------------------------------------------------------------------------
extern "C" void kernel_launch(void* const* d_in, const int* in_sizes, int n_in,
                              void* d_out, int out_size) {
    const float* x    = (const float*)d_in[0];   // [B, L, D] f32
    // d_in[1]: olens (unused)
    const float* W    = (const float*)d_in[2];   // [D, 1]
    const float* bias = (const float*)d_in[3];   // [1]

    float* out = (float*)d_out;
    int write_counts = (out_size >= (int)(OUT_ELEMS + BB)) ? 1 : 0;

    init_kernel<<<(NBLK + 511) / 512, 512>>>();
    fused_kernel<<<NBLK, 256>>>(x, W, bias, out, write_counts);
    {
        long long total4 = (long long)BB * MM * (DD / 4);
        int grid = (int)((total4 + 255) / 256);
        zero_tail_kernel<<<grid, 256>>>(out);
    }
}

// round 5
// speedup vs baseline: 1.3642x; 1.1348x over previous
#include <cuda_runtime.h>

#define BB 32
#define LL 8192
#define DD 256
#define MM (LL/2 + 1)   // 4097

// Scratch (no device allocation allowed)
__device__ float g_s[BB * LL];            // sigmoid scores, 1 MB
__device__ int   g_starts[BB * MM];       // compacted valley starts (sentinel = LL)

// ---------------------------------------------------------------------------
// Kernel 1: s[b,l] = sigmoid(dot(x[b,l,:], W) + bias).
// 4 rows per warp (4 independent accumulators -> high MLP, pipelined
// butterfly reductions), 8 warps per block => 32 rows per block.
// ---------------------------------------------------------------------------
__global__ void __launch_bounds__(256) score_kernel(
    const float* __restrict__ x, const float* __restrict__ W,
    const float* __restrict__ bias)
{
    __shared__ __align__(16) float sW[DD];
    int tid = threadIdx.x;
    sW[tid] = W[tid];                      // blockDim == DD
    __syncthreads();

    int warp = tid >> 5;
    int lane = tid & 31;
    long long row0 = ((long long)blockIdx.x * 8 + warp) * 4;   // 4 rows per warp

    const float4* wv = (const float4*)sW;
    float4 w0 = wv[lane];
    float4 w1 = wv[lane + 32];
    float bv = bias[0];

    float acc[4];
#pragma unroll
    for (int r = 0; r < 4; r++) {
        const float4* src = (const float4*)(x + (row0 + r) * DD);
        float4 v0 = src[lane];
        float4 v1 = src[lane + 32];
        acc[r] = v0.x * w0.x + v0.y * w0.y + v0.z * w0.z + v0.w * w0.w
               + v1.x * w1.x + v1.y * w1.y + v1.z * w1.z + v1.w * w1.w;
    }
#pragma unroll
    for (int o = 16; o; o >>= 1) {
#pragma unroll
        for (int r = 0; r < 4; r++)
            acc[r] += __shfl_xor_sync(0xffffffffu, acc[r], o);
    }
    if (lane == 0) {
        float4 s4;
        s4.x = 1.f / (1.f + expf(-(acc[0] + bv)));
        s4.y = 1.f / (1.f + expf(-(acc[1] + bv)));
        s4.z = 1.f / (1.f + expf(-(acc[2] + bv)));
        s4.w = 1.f / (1.f + expf(-(acc[3] + bv)));
        *(float4*)(g_s + row0) = s4;
    }
}

// ---------------------------------------------------------------------------
// Kernel 2: per-batch strict-local-minima mask + stream compaction.
// One block (1024 threads) per batch. 8 positions per thread.
// ---------------------------------------------------------------------------
__global__ void compact_kernel(float* __restrict__ out_counts, int write_counts) {
    int b = blockIdx.x;
    const float* s = g_s + (long long)b * LL;
    int* starts = g_starts + (long long)b * MM;

    int tid  = threadIdx.x;           // 0..1023
    int lane = tid & 31;
    int wid  = tid >> 5;              // 0..31
    int base = tid * 8;

    bool mk[8];
    int cnt = 0;
#pragma unroll
    for (int i = 0; i < 8; i++) {
        int l = base + i;
        bool m;
        if (l == 0) {
            m = true;                                  // forced valley start
        } else if (l >= LL - 1) {
            m = false;                                 // s_after pad 0, s > 0
        } else {
            float c = s[l];
            m = (c < s[l - 1]) && (c < s[l + 1]);
        }
        mk[i] = m;
        cnt += m ? 1 : 0;
    }

    // warp inclusive scan of cnt
    int v = cnt;
#pragma unroll
    for (int o = 1; o < 32; o <<= 1) {
        int t = __shfl_up_sync(0xffffffffu, v, o);
        if (lane >= o) v += t;
    }
    __shared__ int warpsum[32];
    if (lane == 31) warpsum[wid] = v;
    __syncthreads();
    if (wid == 0) {
        int w = warpsum[lane];
#pragma unroll
        for (int o = 1; o < 32; o <<= 1) {
            int t = __shfl_up_sync(0xffffffffu, w, o);
            if (lane >= o) w += t;
        }
        warpsum[lane] = w;                              // inclusive over warps
    }
    __syncthreads();

    int offset = v - cnt + (wid ? warpsum[wid - 1] : 0);  // exclusive prefix
    int total  = warpsum[31];

#pragma unroll
    for (int i = 0; i < 8; i++) {
        if (mk[i]) starts[offset++] = base + i;
    }

    // sentinel-fill the tail
    for (int k = total + tid; k < MM; k += blockDim.x) starts[k] = LL;

    if (tid == 0 && write_counts) out_counts[b] = (float)total;
}

// ---------------------------------------------------------------------------
// Kernel 3: out[b,k,:] = (s[p]*x[p] + s[p+1]*x[p+1]) / max(s[p]+s[p+1], 1e-6)
// for p = starts[b,k]; zeros for sentinel rows. One float4 per thread.
// ---------------------------------------------------------------------------
__global__ void gather_kernel(const float* __restrict__ x,
                              float* __restrict__ out) {
    long long idx = (long long)blockIdx.x * blockDim.x + threadIdx.x; // vec4 idx
    const long long total4 = (long long)BB * MM * (DD / 4);
    if (idx >= total4) return;

    long long row = idx >> 6;      // (b*MM + k)
    int j = (int)(idx & 63);       // float4 column
    int b = (int)(row / MM);

    int p = g_starts[row];
    float4 o;
    if (p >= LL) {
        o.x = 0.f; o.y = 0.f; o.z = 0.f; o.w = 0.f;
    } else {
        long long xrow = (long long)b * LL + p;
        float s0 = g_s[xrow];
        bool h1 = (p + 1) < LL;
        float s1 = h1 ? g_s[xrow + 1] : 0.f;
        float den = fmaxf(s0 + s1, 1e-6f);

        const float4* x0 = (const float4*)(x + xrow * DD);
        float4 v0 = x0[j];
        float4 v1;
        if (h1) v1 = x0[(DD / 4) + j];
        else { v1.x = 0.f; v1.y = 0.f; v1.z = 0.f; v1.w = 0.f; }

        o.x = (s0 * v0.x + s1 * v1.x) / den;
        o.y = (s0 * v0.y + s1 * v1.y) / den;
        o.z = (s0 * v0.z + s1 * v1.z) / den;
        o.w = (s0 * v0.w + s1 * v1.w) / den;
    }
    ((float4*)out)[idx] = o;
}

// ---------------------------------------------------------------------------
extern "C" void kernel_launch(void* const* d_in, const int* in_sizes, int n_in,
                              void* d_out, int out_size) {
    const float* x    = (const float*)d_in[0];   // [B, L, D] f32
    // d_in[1]: olens (unused by the reference computation)
    const float* W    = (const float*)d_in[2];   // [D, 1] f32
    const float* bias = (const float*)d_in[3];   // [1] f32

    float* out = (float*)d_out;
    const long long out_elems = (long long)BB * MM * DD;   // 33,562,624
    int write_counts = (out_size >= (int)(out_elems + BB)) ? 1 : 0;

    // 1. scores: 32 rows per 256-thread block
    {
        int rows = BB * LL;
        int grid = rows / 32;
        score_kernel<<<grid, 256>>>(x, W, bias);
    }
    // 2. mask + compaction + counts
    {
        compact_kernel<<<BB, 1024>>>(out + out_elems, write_counts);
    }
    // 3. gather + weighted average (+ zero-fill sentinel rows)
    {
        long long total4 = (long long)BB * MM * (DD / 4);
        int grid = (int)((total4 + 255) / 256);
        gather_kernel<<<grid, 256>>>(x, out);
    }
}

// round 6
// speedup vs baseline: 1.6517x; 1.2108x over previous
#include <cuda_runtime.h>

#define BB 32
#define LL 8192
#define DD 256
#define MM (LL/2 + 1)   // 4097

// Scratch (no device allocation allowed)
__device__ float g_s[BB * LL];            // sigmoid scores, 1 MB
__device__ int   g_starts[BB * MM];       // compacted valley starts (sentinel = LL)

// ---------------------------------------------------------------------------
// Kernel 1: s[b,l] = sigmoid(dot(x[b,l,:], W) + bias).
// 4 rows per warp; all 8 float4 loads issued before any FMA (MLP=8/thread),
// streaming loads (no reuse until gather kernel, which is far later).
// ---------------------------------------------------------------------------
__global__ void __launch_bounds__(256) score_kernel(
    const float* __restrict__ x, const float* __restrict__ W,
    const float* __restrict__ bias)
{
    __shared__ __align__(16) float sW[DD];
    int tid = threadIdx.x;
    sW[tid] = W[tid];                      // blockDim == DD
    __syncthreads();

    int warp = tid >> 5;
    int lane = tid & 31;
    long long row0 = ((long long)blockIdx.x * 8 + warp) * 4;   // 4 rows per warp

    const float4* wv = (const float4*)sW;
    float4 w0 = wv[lane];
    float4 w1 = wv[lane + 32];
    float bv = bias[0];

    // front-batched loads: 8 independent LDG.128 in flight
    float4 v0[4], v1[4];
#pragma unroll
    for (int r = 0; r < 4; r++) {
        const float4* src = (const float4*)(x + (row0 + r) * DD);
        v0[r] = __ldcs(src + lane);
        v1[r] = __ldcs(src + lane + 32);
    }

    float acc[4];
#pragma unroll
    for (int r = 0; r < 4; r++) {
        acc[r] = v0[r].x * w0.x + v0[r].y * w0.y + v0[r].z * w0.z + v0[r].w * w0.w
               + v1[r].x * w1.x + v1[r].y * w1.y + v1[r].z * w1.z + v1[r].w * w1.w;
    }
#pragma unroll
    for (int o = 16; o; o >>= 1) {
#pragma unroll
        for (int r = 0; r < 4; r++)
            acc[r] += __shfl_xor_sync(0xffffffffu, acc[r], o);
    }
    if (lane == 0) {
        float4 s4;
        s4.x = 1.f / (1.f + expf(-(acc[0] + bv)));
        s4.y = 1.f / (1.f + expf(-(acc[1] + bv)));
        s4.z = 1.f / (1.f + expf(-(acc[2] + bv)));
        s4.w = 1.f / (1.f + expf(-(acc[3] + bv)));
        *(float4*)(g_s + row0) = s4;
    }
}

// ---------------------------------------------------------------------------
// Kernel 2: per-batch strict-local-minima mask + stream compaction.
// One block (1024 threads) per batch. 8 positions per thread.
// ---------------------------------------------------------------------------
__global__ void compact_kernel(float* __restrict__ out_counts, int write_counts) {
    int b = blockIdx.x;
    const float* s = g_s + (long long)b * LL;
    int* starts = g_starts + (long long)b * MM;

    int tid  = threadIdx.x;           // 0..1023
    int lane = tid & 31;
    int wid  = tid >> 5;              // 0..31
    int base = tid * 8;

    bool mk[8];
    int cnt = 0;
#pragma unroll
    for (int i = 0; i < 8; i++) {
        int l = base + i;
        bool m;
        if (l == 0) {
            m = true;                                  // forced valley start
        } else if (l >= LL - 1) {
            m = false;                                 // s_after pad 0, s > 0
        } else {
            float c = s[l];
            m = (c < s[l - 1]) && (c < s[l + 1]);
        }
        mk[i] = m;
        cnt += m ? 1 : 0;
    }

    // warp inclusive scan of cnt
    int v = cnt;
#pragma unroll
    for (int o = 1; o < 32; o <<= 1) {
        int t = __shfl_up_sync(0xffffffffu, v, o);
        if (lane >= o) v += t;
    }
    __shared__ int warpsum[32];
    if (lane == 31) warpsum[wid] = v;
    __syncthreads();
    if (wid == 0) {
        int w = warpsum[lane];
#pragma unroll
        for (int o = 1; o < 32; o <<= 1) {
            int t = __shfl_up_sync(0xffffffffu, w, o);
            if (lane >= o) w += t;
        }
        warpsum[lane] = w;                              // inclusive over warps
    }
    __syncthreads();

    int offset = v - cnt + (wid ? warpsum[wid - 1] : 0);  // exclusive prefix
    int total  = warpsum[31];

#pragma unroll
    for (int i = 0; i < 8; i++) {
        if (mk[i]) starts[offset++] = base + i;
    }

    // sentinel-fill the tail
    for (int k = total + tid; k < MM; k += blockDim.x) starts[k] = LL;

    if (tid == 0 && write_counts) out_counts[b] = (float)total;
}

// ---------------------------------------------------------------------------
// Kernel 3: out[b,k,:] = (s[p]*x[p] + s[p+1]*x[p+1]) / max(s[p]+s[p+1], 1e-6)
// for p = starts[b,k]; zeros for sentinel rows. One float4 per thread.
// Streaming loads/stores (no reuse), one divide per thread.
// ---------------------------------------------------------------------------
__global__ void __launch_bounds__(256) gather_kernel(
    const float* __restrict__ x, float* __restrict__ out)
{
    long long idx = (long long)blockIdx.x * blockDim.x + threadIdx.x; // vec4 idx
    const long long total4 = (long long)BB * MM * (DD / 4);
    if (idx >= total4) return;

    long long row = idx >> 6;      // (b*MM + k)
    int j = (int)(idx & 63);       // float4 column
    int b = (int)(row / MM);

    int p = __ldg(g_starts + row);
    float4 o;
    if (p >= LL) {
        o.x = 0.f; o.y = 0.f; o.z = 0.f; o.w = 0.f;
    } else {
        long long xrow = (long long)b * LL + p;
        float s0 = g_s[xrow];
        bool h1 = (p + 1) < LL;
        float s1 = h1 ? g_s[xrow + 1] : 0.f;
        float rden = 1.f / fmaxf(s0 + s1, 1e-6f);   // single divide
        float a0 = s0 * rden, a1 = s1 * rden;

        const float4* x0 = (const float4*)(x + xrow * DD);
        float4 v0 = __ldcs(x0 + j);
        float4 v1;
        if (h1) v1 = __ldcs(x0 + (DD / 4) + j);
        else { v1.x = 0.f; v1.y = 0.f; v1.z = 0.f; v1.w = 0.f; }

        o.x = a0 * v0.x + a1 * v1.x;
        o.y = a0 * v0.y + a1 * v1.y;
        o.z = a0 * v0.z + a1 * v1.z;
        o.w = a0 * v0.w + a1 * v1.w;
    }
    __stcs((float4*)out + idx, o);
}

// ---------------------------------------------------------------------------
extern "C" void kernel_launch(void* const* d_in, const int* in_sizes, int n_in,
                              void* d_out, int out_size) {
    const float* x    = (const float*)d_in[0];   // [B, L, D] f32
    // d_in[1]: olens (unused by the reference computation)
    const float* W    = (const float*)d_in[2];   // [D, 1] f32
    const float* bias = (const float*)d_in[3];   // [1] f32

    float* out = (float*)d_out;
    const long long out_elems = (long long)BB * MM * DD;   // 33,562,624
    int write_counts = (out_size >= (int)(out_elems + BB)) ? 1 : 0;

    // 1. scores: 32 rows per 256-thread block
    {
        int rows = BB * LL;
        int grid = rows / 32;
        score_kernel<<<grid, 256>>>(x, W, bias);
    }
    // 2. mask + compaction + counts
    {
        compact_kernel<<<BB, 1024>>>(out + out_elems, write_counts);
    }
    // 3. gather + weighted average (+ zero-fill sentinel rows)
    {
        long long total4 = (long long)BB * MM * (DD / 4);
        int grid = (int)((total4 + 255) / 256);
        gather_kernel<<<grid, 256>>>(x, out);
    }
}